// round 6
// baseline (speedup 1.0000x reference)
#include <cuda_runtime.h>
#include <cuda_fp16.h>
#include <math.h>

// x = (4, 64, 128, 128) fp32, K=7 -> out (4, 49, 16384) fp32
#define BATCH   4
#define CHN     64
#define HT      128
#define WD      128
#define HW      (HT * WD)            // 16384
#define KW      7
#define PADR    3
#define TILEH   32
#define TILEW   16
#define TRH     (TILEH + 2 * PADR)   // 38
#define TRW     (TILEW + 2 * PADR)   // 22
#define NPIX    (TRH * TRW)          // 836
#define NTHREADS 512                 // one center per thread, 16 warps/SM
#define NOFF    (KW * KW)            // 49
#define EPAD    56                   // 49 -> 56 halves (112 B: 7 granules, conflict-free)
#define EPSV    1e-7f

// smem: fp16 tile [NPIX][64] swizzled | fp32 norms [NPIX] | fp16 exps [NTHREADS][EPAD]
#define TILE_HALVES  (NPIX * 64)
#define TILE_BYTES_S (TILE_HALVES * 2)               // 107,008
#define NORM_BYTES   (NPIX * 4)                      // 3,344
#define EXPS_BYTES   (NTHREADS * EPAD * 2)           // 57,344
#define SMEM_BYTES   (TILE_BYTES_S + NORM_BYTES + EXPS_BYTES)  // 167,696 B

__global__ __launch_bounds__(NTHREADS, 1)
void region_sim_kernel(const float* __restrict__ x, float* __restrict__ out) {
    extern __shared__ __align__(16) char smem_raw[];
    __half* tile  = (__half*)smem_raw;                               // [NPIX][64]
    float*  norms = (float*)(smem_raw + TILE_BYTES_S);               // [NPIX]
    __half* exps  = (__half*)(smem_raw + TILE_BYTES_S + NORM_BYTES); // [NTHREADS][EPAD]

    const int b   = blockIdx.z;
    const int w0  = blockIdx.x * TILEW;
    const int h0  = blockIdx.y * TILEH;
    const int tid = threadIdx.x;

    // ---- Phase 1: gmem fp32 -> fp16 smem tile; q fully unrolled for LDG MLP ----
    const float* xb = x + (size_t)b * CHN * HW;
#pragma unroll 1
    for (int p = tid; p < NPIX; p += NTHREADS) {
        int r   = p / TRW;
        int col = p - r * TRW;
        int gh  = h0 - PADR + r;
        int gw  = w0 - PADR + col;
        const bool inb = (gh >= 0 && gh < HT && gw >= 0 && gw < WD);
        const int gi = gh * WD + gw;
        __half2* tp = (__half2*)(tile + p * 64);
        const int sw = p & 7;
#pragma unroll
        for (int q = 0; q < 8; q++) {
            __half2 h0v = __float2half2_rn(0.f), h1v = h0v, h2v = h0v, h3v = h0v;
            if (inb) {
                const float* x0 = xb + (size_t)(q * 8) * HW + gi;
                h0v = __floats2half2_rn(x0[0],      x0[HW]);
                h1v = __floats2half2_rn(x0[2 * HW], x0[3 * HW]);
                h2v = __floats2half2_rn(x0[4 * HW], x0[5 * HW]);
                h3v = __floats2half2_rn(x0[6 * HW], x0[7 * HW]);
            }
            __half2* dst = tp + (size_t)(q ^ sw) * 4;
            dst[0] = h0v; dst[1] = h1v; dst[2] = h2v; dst[3] = h3v;
        }
    }
    __syncthreads();

    // ---- Phase 2: fp32 norms from the fp16 values (consistent cosine) ----
#pragma unroll 1
    for (int p = tid; p < NPIX; p += NTHREADS) {
        const uint4* tp = (const uint4*)(tile + p * 64);
        const int sw = p & 7;
        float4 s = make_float4(0.f, 0.f, 0.f, 0.f);
#pragma unroll
        for (int q = 0; q < 8; q++) {
            uint4 hv = tp[q ^ sw];
            float2 f0 = __half22float2(*(__half2*)&hv.x);
            float2 f1 = __half22float2(*(__half2*)&hv.y);
            float2 f2 = __half22float2(*(__half2*)&hv.z);
            float2 f3 = __half22float2(*(__half2*)&hv.w);
            s.x += f0.x * f0.x + f2.x * f2.x;
            s.y += f0.y * f0.y + f2.y * f2.y;
            s.z += f1.x * f1.x + f3.x * f3.x;
            s.w += f1.y * f1.y + f3.y * f3.y;
        }
        norms[p] = sqrtf((s.x + s.y) + (s.z + s.w));
    }
    __syncthreads();

    // ---- Phase 3: HFMA2 dot; exp(sim) kept as fp16 in smem (no gmem round-trip) ----
    const int lw = tid & (TILEW - 1);
    const int lh = tid >> 4;
    const int colC = PADR + lw;
    const int rC   = PADR + lh;
    const int pC   = rC * TRW + colC;

    __half2 cen[32];
    {
        const uint4* cp = (const uint4*)(tile + pC * 64);
        const int sw = pC & 7;
#pragma unroll
        for (int q = 0; q < 8; q++) {
            uint4 hv = cp[q ^ sw];
            cen[4 * q + 0] = *(__half2*)&hv.x;
            cen[4 * q + 1] = *(__half2*)&hv.y;
            cen[4 * q + 2] = *(__half2*)&hv.z;
            cen[4 * q + 3] = *(__half2*)&hv.w;
        }
    }
    const float nc = norms[pC];
    __half* my_exps = exps + tid * EPAD;

    float den = 0.f;
    const __half2 hz = __float2half2_rn(0.f);

#pragma unroll 1
    for (int o = -PADR; o <= PADR; o++) {
        const int pbase = (rC + o) * TRW + colC;
#pragma unroll
        for (int dj = -PADR; dj <= PADR; dj++) {   // 7 independent chains in flight
            const int pn = pbase + dj;
            const uint4* nb = (const uint4*)(tile + pn * 64);
            const int sw = pn & 7;
            __half2 a0 = hz, a1 = hz, a2 = hz, a3 = hz;
#pragma unroll
            for (int q = 0; q < 8; q++) {
                uint4 hv = nb[q ^ sw];
                a0 = __hfma2(cen[4 * q + 0], *(__half2*)&hv.x, a0);
                a1 = __hfma2(cen[4 * q + 1], *(__half2*)&hv.y, a1);
                a2 = __hfma2(cen[4 * q + 2], *(__half2*)&hv.z, a2);
                a3 = __hfma2(cen[4 * q + 3], *(__half2*)&hv.w, a3);
            }
            float2 f0 = __half22float2(a0);
            float2 f1 = __half22float2(a1);
            float2 f2 = __half22float2(a2);
            float2 f3 = __half22float2(a3);
            float dot = ((f0.x + f0.y) + (f1.x + f1.y))
                      + ((f2.x + f2.y) + (f3.x + f3.y));
            float e = __expf(__fdividef(dot, nc * norms[pn] + EPSV)); // sim in [-1,1]
            __half eh = __float2half_rn(e);
            den += __half2float(eh);               // sum the ROUNDED values: exact softmax
            int kk = (o + PADR) * KW + (dj + PADR);
            my_exps[kk] = eh;
        }
    }

    // ---- Phase 4: normalize from smem, coalesced stores (only gmem writes) ----
    const float ri = __fdividef(1.f, den);
    const size_t obase = (size_t)b * NOFF * HW + (size_t)(h0 + lh) * WD + (w0 + lw);
#pragma unroll 1
    for (int g = 0; g < 6; g++) {                  // 6 x 8 = 48
        uint4 hv = *(const uint4*)(my_exps + g * 8);   // conflict-free LDS.128
        float2 f0 = __half22float2(*(__half2*)&hv.x);
        float2 f1 = __half22float2(*(__half2*)&hv.y);
        float2 f2 = __half22float2(*(__half2*)&hv.z);
        float2 f3 = __half22float2(*(__half2*)&hv.w);
        const size_t ob = obase + (size_t)(g * 8) * HW;
        out[ob]          = f0.x * ri;
        out[ob + HW]     = f0.y * ri;
        out[ob + 2 * HW] = f1.x * ri;
        out[ob + 3 * HW] = f1.y * ri;
        out[ob + 4 * HW] = f2.x * ri;
        out[ob + 5 * HW] = f2.y * ri;
        out[ob + 6 * HW] = f3.x * ri;
        out[ob + 7 * HW] = f3.y * ri;
    }
    out[obase + (size_t)48 * HW] = __half2float(my_exps[48]) * ri;   // tail kk=48
}

extern "C" void kernel_launch(void* const* d_in, const int* in_sizes, int n_in,
                              void* d_out, int out_size) {
    (void)in_sizes; (void)n_in; (void)out_size;
    const float* x = (const float*)d_in[0];
    float* out = (float*)d_out;

    cudaFuncSetAttribute(region_sim_kernel,
                         cudaFuncAttributeMaxDynamicSharedMemorySize, SMEM_BYTES);

    dim3 grid(WD / TILEW, HT / TILEH, BATCH);   // 8 x 4 x 4 = 128 blocks = 1 wave
    region_sim_kernel<<<grid, NTHREADS, SMEM_BYTES>>>(x, out);
}

// round 7
// speedup vs baseline: 1.0816x; 1.0816x over previous
#include <cuda_runtime.h>
#include <cuda_fp16.h>
#include <math.h>

// x = (4, 64, 128, 128) fp32, K=7 -> out (4, 49, 16384) fp32
#define BATCH   4
#define CHN     64
#define HT      128
#define WD      128
#define HW      (HT * WD)            // 16384
#define KW      7
#define PADR    3
#define TILEH   32                   // 2 vertical centers per thread
#define TILEW   16
#define TRH     (TILEH + 2 * PADR)   // 38
#define TRW     (TILEW + 2 * PADR)   // 22
#define NPIX    (TRH * TRW)          // 836
#define NTHREADS 256                 // 128 blocks x 256 thr = 1 wave, 8 warps/SM
#define NOFF    (KW * KW)            // 49
#define EPAD_T  120                  // halves per thread (240B = 15 granules, odd -> CF)
#define EOFF_B  64                   // center B offset (128B aligned)
#define EPSV    1e-7f

// smem: fp16 tile [NPIX][64] swizzled | fp32 norms | fp16 exps [NTHREADS][EPAD_T]
#define TILE_HALVES  (NPIX * 64)
#define TILE_BYTES_S (TILE_HALVES * 2)               // 107,008
#define NORM_BYTES   (NPIX * 4)                      // 3,344
#define EXPS_BYTES   (NTHREADS * EPAD_T * 2)         // 61,440
#define SMEM_BYTES   (TILE_BYTES_S + NORM_BYTES + EXPS_BYTES)  // 171,792 B

// One neighbor pixel: 8 LDS.128 feed HFMA2 dots for center A and/or B.
template<bool UA, bool UB>
__device__ __forceinline__ void neigh(const __half* __restrict__ tile,
                                      const float* __restrict__ norms,
                                      int pn,
                                      const __half2* cA, const __half2* cB,
                                      float nA, float nB,
                                      float& denA, float& denB,
                                      __half* __restrict__ eA, __half* __restrict__ eB,
                                      int kkA, int kkB)
{
    const uint4* nb = (const uint4*)(tile + pn * 64);
    const int sw = pn & 7;
    const __half2 hz = __float2half2_rn(0.f);
    __half2 a0 = hz, a1 = hz, a2 = hz, a3 = hz;
    __half2 b0 = hz, b1 = hz, b2 = hz, b3 = hz;
#pragma unroll
    for (int q = 0; q < 8; q++) {
        uint4 hv = nb[q ^ sw];
        if (UA) {
            a0 = __hfma2(cA[4 * q + 0], *(__half2*)&hv.x, a0);
            a1 = __hfma2(cA[4 * q + 1], *(__half2*)&hv.y, a1);
            a2 = __hfma2(cA[4 * q + 2], *(__half2*)&hv.z, a2);
            a3 = __hfma2(cA[4 * q + 3], *(__half2*)&hv.w, a3);
        }
        if (UB) {
            b0 = __hfma2(cB[4 * q + 0], *(__half2*)&hv.x, b0);
            b1 = __hfma2(cB[4 * q + 1], *(__half2*)&hv.y, b1);
            b2 = __hfma2(cB[4 * q + 2], *(__half2*)&hv.z, b2);
            b3 = __hfma2(cB[4 * q + 3], *(__half2*)&hv.w, b3);
        }
    }
    const float nn = norms[pn];
    if (UA) {
        float2 f0 = __half22float2(a0), f1 = __half22float2(a1);
        float2 f2 = __half22float2(a2), f3 = __half22float2(a3);
        float dot = ((f0.x + f0.y) + (f1.x + f1.y)) + ((f2.x + f2.y) + (f3.x + f3.y));
        float e = __expf(__fdividef(dot, nA * nn + EPSV));
        __half eh = __float2half_rn(e);
        denA += __half2float(eh);
        eA[kkA] = eh;
    }
    if (UB) {
        float2 f0 = __half22float2(b0), f1 = __half22float2(b1);
        float2 f2 = __half22float2(b2), f3 = __half22float2(b3);
        float dot = ((f0.x + f0.y) + (f1.x + f1.y)) + ((f2.x + f2.y) + (f3.x + f3.y));
        float e = __expf(__fdividef(dot, nB * nn + EPSV));
        __half eh = __float2half_rn(e);
        denB += __half2float(eh);
        eB[kkB] = eh;
    }
}

__device__ __forceinline__ void norm_store(const __half* __restrict__ my_exps,
                                           float ri, float* __restrict__ out,
                                           size_t obase)
{
#pragma unroll 1
    for (int g = 0; g < 6; g++) {                  // 6 x 8 = 48
        uint4 hv = *(const uint4*)(my_exps + g * 8);
        float2 f0 = __half22float2(*(__half2*)&hv.x);
        float2 f1 = __half22float2(*(__half2*)&hv.y);
        float2 f2 = __half22float2(*(__half2*)&hv.z);
        float2 f3 = __half22float2(*(__half2*)&hv.w);
        const size_t ob = obase + (size_t)(g * 8) * HW;
        out[ob]          = f0.x * ri;
        out[ob + HW]     = f0.y * ri;
        out[ob + 2 * HW] = f1.x * ri;
        out[ob + 3 * HW] = f1.y * ri;
        out[ob + 4 * HW] = f2.x * ri;
        out[ob + 5 * HW] = f2.y * ri;
        out[ob + 6 * HW] = f3.x * ri;
        out[ob + 7 * HW] = f3.y * ri;
    }
    out[obase + (size_t)48 * HW] = __half2float(my_exps[48]) * ri;
}

__global__ __launch_bounds__(NTHREADS, 1)
void region_sim_kernel(const float* __restrict__ x, float* __restrict__ out) {
    extern __shared__ __align__(16) char smem_raw[];
    __half* tile  = (__half*)smem_raw;                               // [NPIX][64]
    float*  norms = (float*)(smem_raw + TILE_BYTES_S);               // [NPIX]
    __half* exps  = (__half*)(smem_raw + TILE_BYTES_S + NORM_BYTES); // [NTHREADS][EPAD_T]

    const int b   = blockIdx.z;
    const int w0  = blockIdx.x * TILEW;
    const int h0  = blockIdx.y * TILEH;
    const int tid = threadIdx.x;

    // ---- Phase 1: gmem fp32 -> fp16 smem tile; q fully unrolled for LDG MLP ----
    const float* xb = x + (size_t)b * CHN * HW;
#pragma unroll 1
    for (int p = tid; p < NPIX; p += NTHREADS) {
        int r   = p / TRW;
        int col = p - r * TRW;
        int gh  = h0 - PADR + r;
        int gw  = w0 - PADR + col;
        const bool inb = (gh >= 0 && gh < HT && gw >= 0 && gw < WD);
        const int gi = gh * WD + gw;
        __half2* tp = (__half2*)(tile + p * 64);
        const int sw = p & 7;
#pragma unroll
        for (int q = 0; q < 8; q++) {
            __half2 h0v = __float2half2_rn(0.f), h1v = h0v, h2v = h0v, h3v = h0v;
            if (inb) {
                const float* x0 = xb + (size_t)(q * 8) * HW + gi;
                h0v = __floats2half2_rn(x0[0],      x0[HW]);
                h1v = __floats2half2_rn(x0[2 * HW], x0[3 * HW]);
                h2v = __floats2half2_rn(x0[4 * HW], x0[5 * HW]);
                h3v = __floats2half2_rn(x0[6 * HW], x0[7 * HW]);
            }
            __half2* dst = tp + (size_t)(q ^ sw) * 4;
            dst[0] = h0v; dst[1] = h1v; dst[2] = h2v; dst[3] = h3v;
        }
    }
    __syncthreads();

    // ---- Phase 2: fp32 norms from the fp16 values (consistent cosine) ----
#pragma unroll 1
    for (int p = tid; p < NPIX; p += NTHREADS) {
        const uint4* tp = (const uint4*)(tile + p * 64);
        const int sw = p & 7;
        float4 s = make_float4(0.f, 0.f, 0.f, 0.f);
#pragma unroll
        for (int q = 0; q < 8; q++) {
            uint4 hv = tp[q ^ sw];
            float2 f0 = __half22float2(*(__half2*)&hv.x);
            float2 f1 = __half22float2(*(__half2*)&hv.y);
            float2 f2 = __half22float2(*(__half2*)&hv.z);
            float2 f3 = __half22float2(*(__half2*)&hv.w);
            s.x += f0.x * f0.x + f2.x * f2.x;
            s.y += f0.y * f0.y + f2.y * f2.y;
            s.z += f1.x * f1.x + f3.x * f3.x;
            s.w += f1.y * f1.y + f3.y * f3.y;
        }
        norms[p] = sqrtf((s.x + s.y) + (s.z + s.w));
    }
    __syncthreads();

    // ---- Phase 3: two vertical centers per thread; shared neighbor loads ----
    const int lw  = tid & (TILEW - 1);      // 0..15
    const int lhp = tid >> 4;               // 0..15 (row pair)
    const int colC = PADR + lw;
    const int rA   = PADR + 2 * lhp;
    const int pA   = rA * TRW + colC;
    const int pB   = pA + TRW;

    __half2 cenA[32], cenB[32];
    {
        const uint4* ca = (const uint4*)(tile + pA * 64);
        const uint4* cb = (const uint4*)(tile + pB * 64);
        const int swA = pA & 7, swB = pB & 7;
#pragma unroll
        for (int q = 0; q < 8; q++) {
            uint4 ha = ca[q ^ swA];
            uint4 hb = cb[q ^ swB];
            cenA[4 * q + 0] = *(__half2*)&ha.x;  cenB[4 * q + 0] = *(__half2*)&hb.x;
            cenA[4 * q + 1] = *(__half2*)&ha.y;  cenB[4 * q + 1] = *(__half2*)&hb.y;
            cenA[4 * q + 2] = *(__half2*)&ha.z;  cenB[4 * q + 2] = *(__half2*)&hb.z;
            cenA[4 * q + 3] = *(__half2*)&ha.w;  cenB[4 * q + 3] = *(__half2*)&hb.w;
        }
    }
    const float nA = norms[pA];
    const float nB = norms[pB];
    __half* eA = exps + tid * EPAD_T;
    __half* eB = eA + EOFF_B;

    float denA = 0.f, denB = 0.f;

    // o = -3: A only
#pragma unroll
    for (int dj = -PADR; dj <= PADR; dj++) {
        neigh<true, false>(tile, norms, (rA - 3) * TRW + colC + dj,
                           cenA, cenB, nA, nB, denA, denB, eA, eB, dj + 3, 0);
    }
    // o = -2..3: shared rows — one load, two dots
#pragma unroll 1
    for (int o = -2; o <= 3; o++) {
        const int pbase = (rA + o) * TRW + colC;
        const int kA0 = (o + 3) * KW + 3;
        const int kB0 = (o + 2) * KW + 3;
#pragma unroll
        for (int dj = -PADR; dj <= PADR; dj++) {
            neigh<true, true>(tile, norms, pbase + dj,
                              cenA, cenB, nA, nB, denA, denB, eA, eB,
                              kA0 + dj, kB0 + dj);
        }
    }
    // o = +4: B only
#pragma unroll
    for (int dj = -PADR; dj <= PADR; dj++) {
        neigh<false, true>(tile, norms, (rA + 4) * TRW + colC + dj,
                           cenA, cenB, nA, nB, denA, denB, eA, eB,
                           0, 42 + dj + 3);
    }

    // ---- Phase 4: normalize from smem, coalesced stores ----
    const size_t obaseA = (size_t)b * NOFF * HW + (size_t)(h0 + 2 * lhp) * WD + (w0 + lw);
    norm_store(eA, __fdividef(1.f, denA), out, obaseA);
    norm_store(eB, __fdividef(1.f, denB), out, obaseA + WD);
}

extern "C" void kernel_launch(void* const* d_in, const int* in_sizes, int n_in,
                              void* d_out, int out_size) {
    (void)in_sizes; (void)n_in; (void)out_size;
    const float* x = (const float*)d_in[0];
    float* out = (float*)d_out;

    cudaFuncSetAttribute(region_sim_kernel,
                         cudaFuncAttributeMaxDynamicSharedMemorySize, SMEM_BYTES);

    dim3 grid(WD / TILEW, HT / TILEH, BATCH);   // 8 x 4 x 4 = 128 blocks = 1 wave
    region_sim_kernel<<<grid, NTHREADS, SMEM_BYTES>>>(x, out);
}